// round 8
// baseline (speedup 1.0000x reference)
#include <cuda_runtime.h>
#include <math.h>
#include <stdint.h>

#define BATCH   4
#define SEQ     2048
#define DMODEL  512
#define NHEAD   8
#define HDIM    64
#define ROWS    (BATCH * SEQ)        /* 8192 */
#define QKVN    (3 * DMODEL)         /* 1536 */

// Scratch (allocation-free rule: device globals)
__device__ float g_qkv[(size_t)ROWS * QKVN];     // [8192, 1536] tf32 bits
__device__ float g_att[(size_t)ROWS * DMODEL];   // [8192, 512] fp32

__device__ __forceinline__ uint32_t f2tf(float x) {
    uint32_t r;
    asm("cvt.rna.tf32.f32 %0, %1;" : "=r"(r) : "f"(x));
    return r;
}

__device__ __forceinline__ void mma_tf32(float c[4], const uint32_t a[4],
                                         uint32_t b0, uint32_t b1) {
    asm volatile(
        "mma.sync.aligned.m16n8k8.row.col.f32.tf32.tf32.f32 "
        "{%0,%1,%2,%3}, {%4,%5,%6,%7}, {%8,%9}, {%0,%1,%2,%3};"
        : "+f"(c[0]), "+f"(c[1]), "+f"(c[2]), "+f"(c[3])
        : "r"(a[0]), "r"(a[1]), "r"(a[2]), "r"(a[3]), "r"(b0), "r"(b1));
}

__device__ __forceinline__ void cp_async16(uint32_t smem_dst, const void* gsrc) {
    asm volatile("cp.async.cg.shared.global [%0], [%1], 16;"
                 :: "r"(smem_dst), "l"(gsrc) : "memory");
}
__device__ __forceinline__ void cp_async_commit() {
    asm volatile("cp.async.commit_group;" ::: "memory");
}
__device__ __forceinline__ void cp_async_wait1() {
    asm volatile("cp.async.wait_group 1;" ::: "memory");
}

// ---------------------------------------------------------------------------
// TF32 tensor-core GEMM (R6 config): C[M,N] = A[M,K] @ B[K,N], row-major.
// 128x128x16 block tile, 256 threads = 8 warps (2x4), 64x32 warp tile.
// cvt_out != 0: store C as tf32-rounded bit patterns (for attention input).
// ---------------------------------------------------------------------------
#define GBM 128
#define GBN 128
#define GBK 16
#define APAD 20    /* As row stride (words) */
#define BPAD 136   /* Bs row stride (words) */

__global__ __launch_bounds__(256)
void tf32_gemm_kernel(const float* __restrict__ A, const float* __restrict__ B,
                      float* __restrict__ C, int M, int N, int K, int cvt_out) {
    __shared__ uint32_t As[GBM * APAD];   // [m][k] tf32
    __shared__ uint32_t Bs[GBK * BPAD];   // [k][n] tf32

    const int tid  = threadIdx.x;
    const int warp = tid >> 5;
    const int lane = tid & 31;
    const int g = lane >> 2;
    const int c = lane & 3;
    const int wm = warp >> 2;     // 0..1
    const int wn = warp & 3;      // 0..3

    // loaders: A 128x16 (2 thr/row, 8 floats), B 16x128 (16 thr/row, 8 floats)
    const int arow = tid >> 1, acol = (tid & 1) << 3;
    const int brow = tid >> 4, bcol = (tid & 15) << 3;

    const float* Ab = A + (size_t)(blockIdx.y * GBM + arow) * K + acol;
    const float* Bb = B + (size_t)brow * N + blockIdx.x * GBN + bcol;

    float acc[4][4][4];
    #pragma unroll
    for (int mf = 0; mf < 4; mf++)
        #pragma unroll
        for (int nf = 0; nf < 4; nf++)
            #pragma unroll
            for (int j = 0; j < 4; j++) acc[mf][nf][j] = 0.f;

    for (int k0 = 0; k0 < K; k0 += GBK) {
        // ---- stage tiles (tf32 converted) ----
        {
            float4 a0 = *(const float4*)(Ab + k0);
            float4 a1 = *(const float4*)(Ab + k0 + 4);
            uint32_t* da = &As[arow * APAD + acol];
            da[0] = f2tf(a0.x); da[1] = f2tf(a0.y); da[2] = f2tf(a0.z); da[3] = f2tf(a0.w);
            da[4] = f2tf(a1.x); da[5] = f2tf(a1.y); da[6] = f2tf(a1.z); da[7] = f2tf(a1.w);
            float4 b0 = *(const float4*)(Bb + (size_t)k0 * N);
            float4 b1 = *(const float4*)(Bb + (size_t)k0 * N + 4);
            uint32_t* db = &Bs[brow * BPAD + bcol];
            db[0] = f2tf(b0.x); db[1] = f2tf(b0.y); db[2] = f2tf(b0.z); db[3] = f2tf(b0.w);
            db[4] = f2tf(b1.x); db[5] = f2tf(b1.y); db[6] = f2tf(b1.z); db[7] = f2tf(b1.w);
        }
        __syncthreads();

        // ---- compute ----
        #pragma unroll
        for (int kk = 0; kk < GBK; kk += 8) {
            uint32_t af[4][4], bf0[4], bf1[4];
            #pragma unroll
            for (int mf = 0; mf < 4; mf++) {
                const int r0 = wm * 64 + mf * 16 + g;
                af[mf][0] = As[(r0    ) * APAD + kk + c    ];
                af[mf][1] = As[(r0 + 8) * APAD + kk + c    ];
                af[mf][2] = As[(r0    ) * APAD + kk + c + 4];
                af[mf][3] = As[(r0 + 8) * APAD + kk + c + 4];
            }
            #pragma unroll
            for (int nf = 0; nf < 4; nf++) {
                const int n = wn * 32 + nf * 8 + g;
                bf0[nf] = Bs[(kk + c    ) * BPAD + n];
                bf1[nf] = Bs[(kk + c + 4) * BPAD + n];
            }
            #pragma unroll
            for (int mf = 0; mf < 4; mf++)
                #pragma unroll
                for (int nf = 0; nf < 4; nf++)
                    mma_tf32(acc[mf][nf], af[mf], bf0[nf], bf1[nf]);
        }
        __syncthreads();
    }

    // ---- epilogue ----
    #pragma unroll
    for (int mf = 0; mf < 4; mf++) {
        const int r0 = blockIdx.y * GBM + wm * 64 + mf * 16 + g;
        #pragma unroll
        for (int nf = 0; nf < 4; nf++) {
            const int col = blockIdx.x * GBN + wn * 32 + nf * 8 + 2 * c;
            float v0 = acc[mf][nf][0], v1 = acc[mf][nf][1];
            float v2 = acc[mf][nf][2], v3 = acc[mf][nf][3];
            if (cvt_out) {
                v0 = __uint_as_float(f2tf(v0)); v1 = __uint_as_float(f2tf(v1));
                v2 = __uint_as_float(f2tf(v2)); v3 = __uint_as_float(f2tf(v3));
            }
            *(float2*)&C[(size_t)r0 * N + col]       = make_float2(v0, v1);
            *(float2*)&C[(size_t)(r0 + 8) * N + col] = make_float2(v2, v3);
        }
    }
}

// ---------------------------------------------------------------------------
// TF32 flash attention with cp.async double-buffered KV staging.
// Block = 256 threads (8 warps), 128 queries of one (b,h'); streams 64-key
// tiles. K|V are adjacent in the qkv row (words 64..191) -> staged jointly
// as 64x128-word blocks (KVPAD=136). Mask ints prefetched alongside.
// P round-trips through smem warp-locally (reuses Q region).
// ---------------------------------------------------------------------------
#define PAD    72
#define QT     128
#define KVPAD  136
#define KVW    (64 * KVPAD)                   /* words per KV buffer */
#define OFF_KV 9216                           /* after Qs */
#define OFF_MK (OFF_KV + 2 * KVW)             /* 2 mask buffers of 64 ints */
#define ATT_SMEM_WORDS (OFF_MK + 2 * 64)
#define NTILES (SEQ / 64)

__global__ __launch_bounds__(256, 2)
void attn_mma_kernel(const uint32_t* __restrict__ qkv, const int* __restrict__ pmask,
                     float* __restrict__ attout) {
    extern __shared__ uint32_t smu[];
    uint32_t* Qs = smu;                       // [QT][PAD]; later reused as Ps
    uint32_t* KV[2] = { smu + OFF_KV, smu + OFF_KV + KVW };
    int*      MKI[2] = { (int*)(smu + OFF_MK), (int*)(smu + OFF_MK + 64) };

    const int qt = blockIdx.x, h = blockIdx.y, b = blockIdx.z;
    const int tid  = threadIdx.x;
    const int warp = tid >> 5;
    const int lane = tid & 31;
    const int g = lane >> 2;
    const int c = lane & 3;

    const size_t rbase = (size_t)b * (NHEAD * SEQ) + (size_t)h * SEQ;
    const uint32_t* qkv_b = qkv + rbase * (3 * HDIM);

    // Q loader: 2 thr/row (128 rows), 32 words each
    const int qrow  = tid >> 1;
    const int qhalf = (tid & 1) * 32;
    // KV loader: 4 thr/row (64 rows), 32 words (8x16B) each
    const int lrow = tid >> 2;
    const int lcol = (tid & 3) << 5;

    const uint32_t kv0_s = (uint32_t)__cvta_generic_to_shared(&KV[0][lrow * KVPAD + lcol]);
    const uint32_t kv1_s = (uint32_t)__cvta_generic_to_shared(&KV[1][lrow * KVPAD + lcol]);
    const uint32_t kvbuf_s[2] = { kv0_s, kv1_s };
    const uint32_t mk0_s = (uint32_t)__cvta_generic_to_shared(&MKI[0][(tid & 15) * 4]);
    const uint32_t mk1_s = (uint32_t)__cvta_generic_to_shared(&MKI[1][(tid & 15) * 4]);
    const uint32_t mkbuf_s[2] = { mk0_s, mk1_s };

    // ---- stage Q tile (pure copy, already tf32) ----
    {
        const uint4* src = (const uint4*)(qkv_b + (size_t)(qt * QT + qrow) * (3 * HDIM) + qhalf);
        uint4* dst = (uint4*)&Qs[qrow * PAD + qhalf];
        #pragma unroll
        for (int u = 0; u < 8; u++) dst[u] = src[u];
    }

    // ---- issue prefetch of tile 0 into buffer 0 ----
    {
        const uint32_t* src = qkv_b + (size_t)(0 * 64 + lrow) * (3 * HDIM) + HDIM + lcol;
        #pragma unroll
        for (int u = 0; u < 8; u++)
            cp_async16(kv0_s + 16 * u, src + 4 * u);
        if (tid < 16)
            cp_async16(mk0_s, pmask + b * SEQ + (tid & 15) * 4);
        cp_async_commit();
    }
    __syncthreads();

    // ---- Q fragments ----
    uint32_t qa[8][4];
    {
        const int r0 = warp * 16 + g;
        #pragma unroll
        for (int ch = 0; ch < 8; ch++) {
            qa[ch][0] = Qs[(r0    ) * PAD + ch * 8 + c    ];
            qa[ch][1] = Qs[(r0 + 8) * PAD + ch * 8 + c    ];
            qa[ch][2] = Qs[(r0    ) * PAD + ch * 8 + c + 4];
            qa[ch][3] = Qs[(r0 + 8) * PAD + ch * 8 + c + 4];
        }
    }

    float o[8][4];
    #pragma unroll
    for (int nf = 0; nf < 8; nf++)
        #pragma unroll
        for (int j = 0; j < 4; j++) o[nf][j] = 0.f;
    float m0 = -INFINITY, m1 = -INFINITY, l0 = 0.f, l1 = 0.f;

    uint32_t* Ps = Qs;  // reuse after Q frags are in registers

    for (int kt = 0; kt < NTILES; kt++) {
        const int cur = kt & 1, nxt = cur ^ 1;

        // ---- issue prefetch of tile kt+1 into the other buffer ----
        if (kt + 1 < NTILES) {
            const uint32_t* src = qkv_b + (size_t)((kt + 1) * 64 + lrow) * (3 * HDIM) + HDIM + lcol;
            #pragma unroll
            for (int u = 0; u < 8; u++)
                cp_async16(kvbuf_s[nxt] + 16 * u, src + 4 * u);
            if (tid < 16)
                cp_async16(mkbuf_s[nxt], pmask + b * SEQ + (kt + 1) * 64 + (tid & 15) * 4);
        }
        cp_async_commit();
        cp_async_wait1();      // tile kt's group complete (newest group may be in flight)
        __syncthreads();       // cross-thread visibility of buffer `cur`

        const uint32_t* kv = KV[cur];
        const int* mki = MKI[cur];

        // ---- S = Q K^T ----
        float s[8][4];
        #pragma unroll
        for (int kg = 0; kg < 8; kg++) {
            s[kg][0] = s[kg][1] = s[kg][2] = s[kg][3] = 0.f;
            const uint32_t* kbase = &kv[(kg * 8 + g) * KVPAD + c];
            #pragma unroll
            for (int ch = 0; ch < 8; ch++)
                mma_tf32(s[kg], qa[ch], kbase[ch * 8], kbase[ch * 8 + 4]);
        }

        // ---- scale + mask (int mask -> -inf) ----
        #pragma unroll
        for (int kg = 0; kg < 8; kg++) {
            const int col0 = kg * 8 + 2 * c;
            const bool v0 = mki[col0] != 0, v1 = mki[col0 + 1] != 0;
            s[kg][0] = v0 ? s[kg][0] * 0.125f : -INFINITY;
            s[kg][1] = v1 ? s[kg][1] * 0.125f : -INFINITY;
            s[kg][2] = v0 ? s[kg][2] * 0.125f : -INFINITY;
            s[kg][3] = v1 ? s[kg][3] * 0.125f : -INFINITY;
        }

        // ---- online softmax ----
        float mx0 = -INFINITY, mx1 = -INFINITY;
        #pragma unroll
        for (int kg = 0; kg < 8; kg++) {
            mx0 = fmaxf(mx0, fmaxf(s[kg][0], s[kg][1]));
            mx1 = fmaxf(mx1, fmaxf(s[kg][2], s[kg][3]));
        }
        mx0 = fmaxf(mx0, __shfl_xor_sync(0xffffffffu, mx0, 1));
        mx0 = fmaxf(mx0, __shfl_xor_sync(0xffffffffu, mx0, 2));
        mx1 = fmaxf(mx1, __shfl_xor_sync(0xffffffffu, mx1, 1));
        mx1 = fmaxf(mx1, __shfl_xor_sync(0xffffffffu, mx1, 2));

        float mn0 = fmaxf(m0, mx0), mn1 = fmaxf(m1, mx1);
        float sc0 = (mn0 == -INFINITY) ? 1.f : __expf(m0 - mn0);
        float sc1 = (mn1 == -INFINITY) ? 1.f : __expf(m1 - mn1);

        float sum0 = 0.f, sum1 = 0.f;
        {
            const int r0 = warp * 16 + g;
            uint32_t* pdst0 = &Ps[(r0    ) * PAD + 2 * c];
            uint32_t* pdst1 = &Ps[(r0 + 8) * PAD + 2 * c];
            #pragma unroll
            for (int kg = 0; kg < 8; kg++) {
                float p0 = (s[kg][0] == -INFINITY) ? 0.f : __expf(s[kg][0] - mn0);
                float p1 = (s[kg][1] == -INFINITY) ? 0.f : __expf(s[kg][1] - mn0);
                float p2 = (s[kg][2] == -INFINITY) ? 0.f : __expf(s[kg][2] - mn1);
                float p3 = (s[kg][3] == -INFINITY) ? 0.f : __expf(s[kg][3] - mn1);
                uint32_t t0 = f2tf(p0), t1 = f2tf(p1), t2 = f2tf(p2), t3 = f2tf(p3);
                sum0 += __uint_as_float(t0) + __uint_as_float(t1);
                sum1 += __uint_as_float(t2) + __uint_as_float(t3);
                *(uint2*)(pdst0 + kg * 8) = make_uint2(t0, t1);
                *(uint2*)(pdst1 + kg * 8) = make_uint2(t2, t3);
            }
        }
        sum0 += __shfl_xor_sync(0xffffffffu, sum0, 1);
        sum0 += __shfl_xor_sync(0xffffffffu, sum0, 2);
        sum1 += __shfl_xor_sync(0xffffffffu, sum1, 1);
        sum1 += __shfl_xor_sync(0xffffffffu, sum1, 2);

        l0 = l0 * sc0 + sum0;  m0 = mn0;
        l1 = l1 * sc1 + sum1;  m1 = mn1;

        #pragma unroll
        for (int nf = 0; nf < 8; nf++) {
            o[nf][0] *= sc0; o[nf][1] *= sc0;
            o[nf][2] *= sc1; o[nf][3] *= sc1;
        }
        __syncwarp();   // Ps rows are warp-private

        // ---- O += P V  (V at word offset 64 within KV rows) ----
        #pragma unroll
        for (int ch = 0; ch < 8; ch++) {
            uint32_t pa[4];
            const int r0 = warp * 16 + g;
            pa[0] = Ps[(r0    ) * PAD + ch * 8 + c    ];
            pa[1] = Ps[(r0 + 8) * PAD + ch * 8 + c    ];
            pa[2] = Ps[(r0    ) * PAD + ch * 8 + c + 4];
            pa[3] = Ps[(r0 + 8) * PAD + ch * 8 + c + 4];
            const uint32_t* vb0 = &kv[(ch * 8 + c    ) * KVPAD + 64 + g];
            const uint32_t* vb1 = &kv[(ch * 8 + c + 4) * KVPAD + 64 + g];
            #pragma unroll
            for (int nf = 0; nf < 8; nf++)
                mma_tf32(o[nf], pa, vb0[nf * 8], vb1[nf * 8]);
        }
        __syncthreads();  // all reads of buffer `cur` done before it is refilled at kt+2
    }

    // ---- epilogue ----
    {
        const int r0 = warp * 16 + g;
        const int row0 = qt * QT + r0, row1 = row0 + 8;
        float inv0 = (l0 > 0.f) ? (1.f / l0) : 0.f;
        float inv1 = (l1 > 0.f) ? (1.f / l1) : 0.f;
        if (pmask[b * SEQ + row0] == 0) inv0 = 0.f;
        if (pmask[b * SEQ + row1] == 0) inv1 = 0.f;
        float* out0 = attout + (rbase + row0) * HDIM + 2 * c;
        float* out1 = attout + (rbase + row1) * HDIM + 2 * c;
        #pragma unroll
        for (int nf = 0; nf < 8; nf++) {
            *(float2*)(out0 + nf * 8) = make_float2(o[nf][0] * inv0, o[nf][1] * inv0);
            *(float2*)(out1 + nf * 8) = make_float2(o[nf][2] * inv1, o[nf][3] * inv1);
        }
    }
}

// ---------------------------------------------------------------------------
extern "C" void kernel_launch(void* const* d_in, const int* in_sizes, int n_in,
                              void* d_out, int out_size) {
    const float* x     = (const float*)d_in[0];
    const int*   pmask = (const int*)d_in[2];
    const float* Wqkv  = (const float*)d_in[3];
    const float* Wout  = (const float*)d_in[4];
    float* out = (float*)d_out;

    float *qkv_p = nullptr, *att_p = nullptr;
    cudaGetSymbolAddress((void**)&qkv_p, g_qkv);
    cudaGetSymbolAddress((void**)&att_p, g_att);

    const int attn_smem = ATT_SMEM_WORDS * (int)sizeof(uint32_t);
    cudaFuncSetAttribute(attn_mma_kernel, cudaFuncAttributeMaxDynamicSharedMemorySize, attn_smem);

    // 1) QKV = x @ W_qkv : [8192,512] @ [512,1536]  (output tf32-rounded bits)
    tf32_gemm_kernel<<<dim3(QKVN / GBN, ROWS / GBM), 256>>>(x, Wqkv, qkv_p, ROWS, QKVN, DMODEL, 1);

    // 2) tf32 tensor-core attention over the reshaped (flat) layout
    attn_mma_kernel<<<dim3(SEQ / QT, NHEAD, BATCH), 256, attn_smem>>>(
        (const uint32_t*)qkv_p, pmask, att_p);

    // 3) out = att @ W_out : [8192,512] @ [512,512]  (plain fp32 output)
    tf32_gemm_kernel<<<dim3(DMODEL / GBN, ROWS / GBM), 256>>>(att_p, Wout, out, ROWS, DMODEL, DMODEL, 0);
}

// round 9
// speedup vs baseline: 1.1617x; 1.1617x over previous
#include <cuda_runtime.h>
#include <math.h>
#include <stdint.h>

#define BATCH   4
#define SEQ     2048
#define DMODEL  512
#define NHEAD   8
#define HDIM    64
#define ROWS    (BATCH * SEQ)        /* 8192 */
#define QKVN    (3 * DMODEL)         /* 1536 */

// Scratch (allocation-free rule: device globals)
__device__ float g_qkv[(size_t)ROWS * QKVN];     // [8192, 1536] tf32 bits
__device__ float g_att[(size_t)ROWS * DMODEL];   // [8192, 512] fp32

__device__ __forceinline__ uint32_t f2tf(float x) {
    uint32_t r;
    asm("cvt.rna.tf32.f32 %0, %1;" : "=r"(r) : "f"(x));
    return r;
}

__device__ __forceinline__ void mma_tf32(float c[4], const uint32_t a[4],
                                         uint32_t b0, uint32_t b1) {
    asm volatile(
        "mma.sync.aligned.m16n8k8.row.col.f32.tf32.tf32.f32 "
        "{%0,%1,%2,%3}, {%4,%5,%6,%7}, {%8,%9}, {%0,%1,%2,%3};"
        : "+f"(c[0]), "+f"(c[1]), "+f"(c[2]), "+f"(c[3])
        : "r"(a[0]), "r"(a[1]), "r"(a[2]), "r"(a[3]), "r"(b0), "r"(b1));
}

__device__ __forceinline__ void cp_async16(uint32_t smem_dst, const void* gsrc) {
    asm volatile("cp.async.cg.shared.global [%0], [%1], 16;"
                 :: "r"(smem_dst), "l"(gsrc) : "memory");
}
__device__ __forceinline__ void cp_async_commit() {
    asm volatile("cp.async.commit_group;" ::: "memory");
}
__device__ __forceinline__ void cp_async_wait1() {
    asm volatile("cp.async.wait_group 1;" ::: "memory");
}

// ---------------------------------------------------------------------------
// TF32 tensor-core GEMM, 2-stage cp.async pipeline.
// C[M,N] = A[M,K] @ B[K,N], row-major. 128x128x16 block tile, 256 threads =
// 8 warps (2x4), 64x32 warp tile. Raw fp32 staged via cp.async; tf32
// conversion (cvt.rna) applied at fragment load — numerically identical to
// converting at stage time. cvt_out != 0: C stored tf32-rounded.
// ---------------------------------------------------------------------------
#define GBM 128
#define GBN 128
#define GBK 16
#define APAD 20    /* As row stride (words) */
#define BPAD 136   /* Bs row stride (words) */
#define AW (GBM * APAD)
#define BW (GBK * BPAD)

__global__ __launch_bounds__(256)
void tf32_gemm_kernel(const float* __restrict__ A, const float* __restrict__ B,
                      float* __restrict__ C, int M, int N, int K, int cvt_out) {
    __shared__ float As[2][AW];   // [m][k] raw fp32
    __shared__ float Bs[2][BW];   // [k][n] raw fp32

    const int tid  = threadIdx.x;
    const int warp = tid >> 5;
    const int lane = tid & 31;
    const int g = lane >> 2;
    const int c = lane & 3;
    const int wm = warp >> 2;     // 0..1
    const int wn = warp & 3;      // 0..3

    // loaders: A 128x16 (2 thr/row, 8 floats), B 16x128 (16 thr/row, 8 floats)
    const int arow = tid >> 1, acol = (tid & 1) << 3;
    const int brow = tid >> 4, bcol = (tid & 15) << 3;

    const float* Ag = A + (size_t)(blockIdx.y * GBM + arow) * K + acol;
    const float* Bg = B + (size_t)brow * N + blockIdx.x * GBN + bcol;

    const uint32_t a_dst[2] = {
        (uint32_t)__cvta_generic_to_shared(&As[0][arow * APAD + acol]),
        (uint32_t)__cvta_generic_to_shared(&As[1][arow * APAD + acol]) };
    const uint32_t b_dst[2] = {
        (uint32_t)__cvta_generic_to_shared(&Bs[0][brow * BPAD + bcol]),
        (uint32_t)__cvta_generic_to_shared(&Bs[1][brow * BPAD + bcol]) };

    float acc[4][4][4];
    #pragma unroll
    for (int mf = 0; mf < 4; mf++)
        #pragma unroll
        for (int nf = 0; nf < 4; nf++)
            #pragma unroll
            for (int j = 0; j < 4; j++) acc[mf][nf][j] = 0.f;

    const int nIter = K / GBK;

    // prologue: prefetch tile 0 into buffer 0
    cp_async16(a_dst[0],      Ag);
    cp_async16(a_dst[0] + 16, Ag + 4);
    cp_async16(b_dst[0],      Bg);
    cp_async16(b_dst[0] + 16, Bg + 4);
    cp_async_commit();

    for (int it = 0; it < nIter; it++) {
        const int cur = it & 1, nxt = cur ^ 1;

        // prefetch tile it+1 into the other buffer
        if (it + 1 < nIter) {
            const int k0 = (it + 1) * GBK;
            cp_async16(a_dst[nxt],      Ag + k0);
            cp_async16(a_dst[nxt] + 16, Ag + k0 + 4);
            cp_async16(b_dst[nxt],      Bg + (size_t)k0 * N);
            cp_async16(b_dst[nxt] + 16, Bg + (size_t)k0 * N + 4);
        }
        cp_async_commit();
        cp_async_wait1();      // tile it's group complete (newest may fly)
        __syncthreads();

        const float* Asc = As[cur];
        const float* Bsc = Bs[cur];

        #pragma unroll
        for (int kk = 0; kk < GBK; kk += 8) {
            uint32_t af[4][4], bf0[4], bf1[4];
            #pragma unroll
            for (int mf = 0; mf < 4; mf++) {
                const int r0 = wm * 64 + mf * 16 + g;
                af[mf][0] = f2tf(Asc[(r0    ) * APAD + kk + c    ]);
                af[mf][1] = f2tf(Asc[(r0 + 8) * APAD + kk + c    ]);
                af[mf][2] = f2tf(Asc[(r0    ) * APAD + kk + c + 4]);
                af[mf][3] = f2tf(Asc[(r0 + 8) * APAD + kk + c + 4]);
            }
            #pragma unroll
            for (int nf = 0; nf < 4; nf++) {
                const int n = wn * 32 + nf * 8 + g;
                bf0[nf] = f2tf(Bsc[(kk + c    ) * BPAD + n]);
                bf1[nf] = f2tf(Bsc[(kk + c + 4) * BPAD + n]);
            }
            #pragma unroll
            for (int mf = 0; mf < 4; mf++)
                #pragma unroll
                for (int nf = 0; nf < 4; nf++)
                    mma_tf32(acc[mf][nf], af[mf], bf0[nf], bf1[nf]);
        }
        __syncthreads();   // all reads of `cur` done before it is refilled
    }

    // ---- epilogue ----
    #pragma unroll
    for (int mf = 0; mf < 4; mf++) {
        const int r0 = blockIdx.y * GBM + wm * 64 + mf * 16 + g;
        #pragma unroll
        for (int nf = 0; nf < 4; nf++) {
            const int col = blockIdx.x * GBN + wn * 32 + nf * 8 + 2 * c;
            float v0 = acc[mf][nf][0], v1 = acc[mf][nf][1];
            float v2 = acc[mf][nf][2], v3 = acc[mf][nf][3];
            if (cvt_out) {
                v0 = __uint_as_float(f2tf(v0)); v1 = __uint_as_float(f2tf(v1));
                v2 = __uint_as_float(f2tf(v2)); v3 = __uint_as_float(f2tf(v3));
            }
            *(float2*)&C[(size_t)r0 * N + col]       = make_float2(v0, v1);
            *(float2*)&C[(size_t)(r0 + 8) * N + col] = make_float2(v2, v3);
        }
    }
}

// ---------------------------------------------------------------------------
// TF32 tensor-core flash attention (known-best R7 config, restored exactly).
// Block = 256 threads (8 warps), 128 queries of one (b,h'); streams 64-key
// tiles. qkv holds pre-rounded tf32 bits -> staging is pure vectorized copy.
// P round-trips through smem warp-locally (reuses Q region).
// ---------------------------------------------------------------------------
#define PAD 72
#define QT  128
#define ATT_SMEM_WORDS (QT * PAD + 2 * 64 * PAD + 64)

__global__ __launch_bounds__(256)
void attn_mma_kernel(const uint32_t* __restrict__ qkv, const int* __restrict__ pmask,
                     float* __restrict__ attout) {
    extern __shared__ uint32_t smu[];
    uint32_t* Qs = smu;                  // [QT][PAD]; later reused as Ps
    uint32_t* Ks = Qs + QT * PAD;        // [64][PAD]
    uint32_t* Vs = Ks + 64 * PAD;        // [64][PAD]
    float*    mk = (float*)(Vs + 64 * PAD);  // [64]

    const int qt = blockIdx.x, h = blockIdx.y, b = blockIdx.z;
    const int tid  = threadIdx.x;
    const int warp = tid >> 5;
    const int lane = tid & 31;
    const int g = lane >> 2;
    const int c = lane & 3;

    const size_t rbase = (size_t)b * (NHEAD * SEQ) + (size_t)h * SEQ;
    const uint32_t* qkv_b = qkv + rbase * (3 * HDIM);

    // Q loader: 2 thr/row (128 rows), 32 words each
    const int qrow  = tid >> 1;
    const int qhalf = (tid & 1) * 32;
    // KV loader: 4 thr/row (64 rows), 16 words each
    const int lrow = tid >> 2;
    const int lcol = (tid & 3) << 4;

    // ---- stage Q tile (pure copy, already tf32) ----
    {
        const uint4* src = (const uint4*)(qkv_b + (size_t)(qt * QT + qrow) * (3 * HDIM) + qhalf);
        uint4* dst = (uint4*)&Qs[qrow * PAD + qhalf];
        #pragma unroll
        for (int u = 0; u < 8; u++) dst[u] = src[u];
    }
    __syncthreads();

    // ---- Q fragments ----
    uint32_t qa[8][4];
    {
        const int r0 = warp * 16 + g;
        #pragma unroll
        for (int ch = 0; ch < 8; ch++) {
            qa[ch][0] = Qs[(r0    ) * PAD + ch * 8 + c    ];
            qa[ch][1] = Qs[(r0 + 8) * PAD + ch * 8 + c    ];
            qa[ch][2] = Qs[(r0    ) * PAD + ch * 8 + c + 4];
            qa[ch][3] = Qs[(r0 + 8) * PAD + ch * 8 + c + 4];
        }
    }

    float o[8][4];
    #pragma unroll
    for (int nf = 0; nf < 8; nf++)
        #pragma unroll
        for (int j = 0; j < 4; j++) o[nf][j] = 0.f;
    float m0 = -INFINITY, m1 = -INFINITY, l0 = 0.f, l1 = 0.f;

    uint32_t* Ps = Qs;  // reuse after Q frags are in registers

    for (int kt = 0; kt < SEQ / 64; kt++) {
        __syncthreads();   // prior-iteration reads of Ks/Vs/mk complete

        // ---- stage K, V tiles (pure copy) + mask ----
        {
            const uint4* srck = (const uint4*)(qkv_b + (size_t)(kt * 64 + lrow) * (3 * HDIM) + HDIM + lcol);
            const uint4* srcv = (const uint4*)(qkv_b + (size_t)(kt * 64 + lrow) * (3 * HDIM) + 2 * HDIM + lcol);
            uint4* dk = (uint4*)&Ks[lrow * PAD + lcol];
            uint4* dv = (uint4*)&Vs[lrow * PAD + lcol];
            #pragma unroll
            for (int u = 0; u < 4; u++) { dk[u] = srck[u]; dv[u] = srcv[u]; }
            if (tid < 64)
                mk[tid] = (pmask[b * SEQ + kt * 64 + tid] != 0) ? 0.f : -INFINITY;
        }
        __syncthreads();

        // ---- S = Q K^T ----
        float s[8][4];
        #pragma unroll
        for (int kg = 0; kg < 8; kg++) {
            s[kg][0] = s[kg][1] = s[kg][2] = s[kg][3] = 0.f;
            const uint32_t* kbase = &Ks[(kg * 8 + g) * PAD + c];
            #pragma unroll
            for (int ch = 0; ch < 8; ch++)
                mma_tf32(s[kg], qa[ch], kbase[ch * 8], kbase[ch * 8 + 4]);
        }

        // ---- scale + mask ----
        #pragma unroll
        for (int kg = 0; kg < 8; kg++) {
            const int col0 = kg * 8 + 2 * c;
            float mk0 = mk[col0], mk1 = mk[col0 + 1];
            s[kg][0] = s[kg][0] * 0.125f + mk0;
            s[kg][1] = s[kg][1] * 0.125f + mk1;
            s[kg][2] = s[kg][2] * 0.125f + mk0;
            s[kg][3] = s[kg][3] * 0.125f + mk1;
        }

        // ---- online softmax ----
        float mx0 = -INFINITY, mx1 = -INFINITY;
        #pragma unroll
        for (int kg = 0; kg < 8; kg++) {
            mx0 = fmaxf(mx0, fmaxf(s[kg][0], s[kg][1]));
            mx1 = fmaxf(mx1, fmaxf(s[kg][2], s[kg][3]));
        }
        mx0 = fmaxf(mx0, __shfl_xor_sync(0xffffffffu, mx0, 1));
        mx0 = fmaxf(mx0, __shfl_xor_sync(0xffffffffu, mx0, 2));
        mx1 = fmaxf(mx1, __shfl_xor_sync(0xffffffffu, mx1, 1));
        mx1 = fmaxf(mx1, __shfl_xor_sync(0xffffffffu, mx1, 2));

        float mn0 = fmaxf(m0, mx0), mn1 = fmaxf(m1, mx1);
        float sc0 = (mn0 == -INFINITY) ? 1.f : __expf(m0 - mn0);
        float sc1 = (mn1 == -INFINITY) ? 1.f : __expf(m1 - mn1);

        float sum0 = 0.f, sum1 = 0.f;
        {
            const int r0 = warp * 16 + g;
            uint32_t* pdst0 = &Ps[(r0    ) * PAD + 2 * c];
            uint32_t* pdst1 = &Ps[(r0 + 8) * PAD + 2 * c];
            #pragma unroll
            for (int kg = 0; kg < 8; kg++) {
                float p0 = (s[kg][0] == -INFINITY) ? 0.f : __expf(s[kg][0] - mn0);
                float p1 = (s[kg][1] == -INFINITY) ? 0.f : __expf(s[kg][1] - mn0);
                float p2 = (s[kg][2] == -INFINITY) ? 0.f : __expf(s[kg][2] - mn1);
                float p3 = (s[kg][3] == -INFINITY) ? 0.f : __expf(s[kg][3] - mn1);
                uint32_t t0 = f2tf(p0), t1 = f2tf(p1), t2 = f2tf(p2), t3 = f2tf(p3);
                sum0 += __uint_as_float(t0) + __uint_as_float(t1);
                sum1 += __uint_as_float(t2) + __uint_as_float(t3);
                *(uint2*)(pdst0 + kg * 8) = make_uint2(t0, t1);
                *(uint2*)(pdst1 + kg * 8) = make_uint2(t2, t3);
            }
        }
        sum0 += __shfl_xor_sync(0xffffffffu, sum0, 1);
        sum0 += __shfl_xor_sync(0xffffffffu, sum0, 2);
        sum1 += __shfl_xor_sync(0xffffffffu, sum1, 1);
        sum1 += __shfl_xor_sync(0xffffffffu, sum1, 2);

        l0 = l0 * sc0 + sum0;  m0 = mn0;
        l1 = l1 * sc1 + sum1;  m1 = mn1;

        #pragma unroll
        for (int nf = 0; nf < 8; nf++) {
            o[nf][0] *= sc0; o[nf][1] *= sc0;
            o[nf][2] *= sc1; o[nf][3] *= sc1;
        }
        __syncwarp();   // Ps rows are warp-private

        // ---- O += P V ----
        #pragma unroll
        for (int ch = 0; ch < 8; ch++) {
            uint32_t pa[4];
            const int r0 = warp * 16 + g;
            pa[0] = Ps[(r0    ) * PAD + ch * 8 + c    ];
            pa[1] = Ps[(r0 + 8) * PAD + ch * 8 + c    ];
            pa[2] = Ps[(r0    ) * PAD + ch * 8 + c + 4];
            pa[3] = Ps[(r0 + 8) * PAD + ch * 8 + c + 4];
            const uint32_t* vb0 = &Vs[(ch * 8 + c    ) * PAD + g];
            const uint32_t* vb1 = &Vs[(ch * 8 + c + 4) * PAD + g];
            #pragma unroll
            for (int nf = 0; nf < 8; nf++)
                mma_tf32(o[nf], pa, vb0[nf * 8], vb1[nf * 8]);
        }
        __syncwarp();
    }

    // ---- epilogue ----
    {
        const int r0 = warp * 16 + g;
        const int row0 = qt * QT + r0, row1 = row0 + 8;
        float inv0 = (l0 > 0.f) ? (1.f / l0) : 0.f;
        float inv1 = (l1 > 0.f) ? (1.f / l1) : 0.f;
        if (pmask[b * SEQ + row0] == 0) inv0 = 0.f;
        if (pmask[b * SEQ + row1] == 0) inv1 = 0.f;
        float* out0 = attout + (rbase + row0) * HDIM + 2 * c;
        float* out1 = attout + (rbase + row1) * HDIM + 2 * c;
        #pragma unroll
        for (int nf = 0; nf < 8; nf++) {
            *(float2*)(out0 + nf * 8) = make_float2(o[nf][0] * inv0, o[nf][1] * inv0);
            *(float2*)(out1 + nf * 8) = make_float2(o[nf][2] * inv1, o[nf][3] * inv1);
        }
    }
}

// ---------------------------------------------------------------------------
extern "C" void kernel_launch(void* const* d_in, const int* in_sizes, int n_in,
                              void* d_out, int out_size) {
    const float* x     = (const float*)d_in[0];
    const int*   pmask = (const int*)d_in[2];
    const float* Wqkv  = (const float*)d_in[3];
    const float* Wout  = (const float*)d_in[4];
    float* out = (float*)d_out;

    float *qkv_p = nullptr, *att_p = nullptr;
    cudaGetSymbolAddress((void**)&qkv_p, g_qkv);
    cudaGetSymbolAddress((void**)&att_p, g_att);

    const int attn_smem = ATT_SMEM_WORDS * (int)sizeof(uint32_t);
    cudaFuncSetAttribute(attn_mma_kernel, cudaFuncAttributeMaxDynamicSharedMemorySize, attn_smem);

    // 1) QKV = x @ W_qkv : [8192,512] @ [512,1536]  (output tf32-rounded bits)
    tf32_gemm_kernel<<<dim3(QKVN / GBN, ROWS / GBM), 256>>>(x, Wqkv, qkv_p, ROWS, QKVN, DMODEL, 1);

    // 2) tf32 tensor-core attention over the reshaped (flat) layout
    attn_mma_kernel<<<dim3(SEQ / QT, NHEAD, BATCH), 256, attn_smem>>>(
        (const uint32_t*)qkv_p, pmask, att_p);

    // 3) out = att @ W_out : [8192,512] @ [512,512]  (plain fp32 output)
    tf32_gemm_kernel<<<dim3(DMODEL / GBN, ROWS / GBM), 256>>>(att_p, Wout, out, ROWS, DMODEL, DMODEL, 0);
}